// round 3
// baseline (speedup 1.0000x reference)
#include <cuda_runtime.h>
#include <math.h>

#define NN 20000
#define EE 640000

// ---------------- scratch (device globals; no allocation) ----------------
__device__ float g_fs[NN * 32];          // TP-input scalars after Linear1
__device__ float g_ss[NN * 32];          // self-connection scalars
__device__ float g_fv[NN * 96];          // TP-input vectors [N][32][3]
__device__ float g_sv[NN * 96];          // self-connection vectors
__device__ float g_w[(size_t)EE * 128];  // per-edge MLP weights [E][4*32]
__device__ float g_ns[NN * 64];          // scattered mid scalars
__device__ float g_nv[NN * 192];         // scattered mid vectors [N][64][3]
__device__ int   g_cnt[NN];
__device__ int   g_row[NN + 1];
__device__ int   g_cur[NN];
__device__ int   g_ord[EE];

// ---------------- packed f32x2 helpers ----------------
typedef unsigned long long ull;

__device__ __forceinline__ ull pk2(float a, float b) {
    ull r; asm("mov.b64 %0,{%1,%2};" : "=l"(r) : "f"(a), "f"(b)); return r;
}
__device__ __forceinline__ void upk2(ull v, float& a, float& b) {
    asm("mov.b64 {%0,%1},%2;" : "=f"(a), "=f"(b) : "l"(v));
}
__device__ __forceinline__ ull fma2(ull a, ull b, ull c) {
    ull r; asm("fma.rn.f32x2 %0,%1,%2,%3;" : "=l"(r) : "l"(a), "l"(b), "l"(c)); return r;
}
__device__ __forceinline__ ull mul2(ull a, ull b) {
    ull r; asm("mul.rn.f32x2 %0,%1,%2;" : "=l"(r) : "l"(a), "l"(b)); return r;
}
__device__ __forceinline__ ull add2(ull a, ull b) {
    ull r; asm("add.rn.f32x2 %0,%1,%2;" : "=l"(r) : "l"(a), "l"(b)); return r;
}
__device__ __forceinline__ float tanh_ap(float x) {
    float r; asm("tanh.approx.f32 %0,%1;" : "=f"(r) : "f"(x)); return r;
}
__device__ __forceinline__ float gelu_f(float v) {
    float u = 0.7978845608028654f * (v + 0.044715f * v * v * v);
    return 0.5f * v * (1.0f + tanh_ap(u));
}
// gelu on a packed pair
__device__ __forceinline__ ull gelu2(ull v) {
    const ull C0 = pk2(0.7978845608028654f, 0.7978845608028654f);
    const ull C1 = pk2(0.03567740814183418f, 0.03567740814183418f);
    const ull H2 = pk2(0.5f, 0.5f);
    const ull O2 = pk2(1.0f, 1.0f);
    ull vv = mul2(v, v);
    ull u  = mul2(fma2(vv, C1, C0), v);
    float ulo, uhi; upk2(u, ulo, uhi);
    ull t = pk2(tanh_ap(ulo), tanh_ap(uhi));
    return mul2(mul2(v, H2), add2(O2, t));
}

// ---------------- sort-by-dst machinery ----------------
__global__ void k_zero() {
    int i = blockIdx.x * blockDim.x + threadIdx.x;
    if (i < NN) g_cnt[i] = 0;
}

__global__ void k_hist(const int* __restrict__ dst) {
    int e = blockIdx.x * blockDim.x + threadIdx.x;
    if (e < EE) atomicAdd(&g_cnt[dst[e]], 1);
}

__global__ void k_scan() {
    __shared__ int part[1024];
    int t = threadIdx.x;
    const int CH = (NN + 1023) / 1024;  // 20
    int base = t * CH;
    int s = 0;
    for (int i = 0; i < CH; i++) {
        int idx = base + i;
        if (idx < NN) s += g_cnt[idx];
    }
    part[t] = s;
    __syncthreads();
    for (int off = 1; off < 1024; off <<= 1) {
        int v = 0;
        if (t >= off) v = part[t - off];
        __syncthreads();
        part[t] += v;
        __syncthreads();
    }
    int run = (t == 0) ? 0 : part[t - 1];
    for (int i = 0; i < CH; i++) {
        int idx = base + i;
        if (idx < NN) {
            g_row[idx] = run;
            g_cur[idx] = run;
            run += g_cnt[idx];
        }
    }
    if (t == 1023) g_row[NN] = part[1023];
}

__global__ void k_place(const int* __restrict__ dst) {
    int e = blockIdx.x * blockDim.x + threadIdx.x;
    if (e < EE) {
        int p = atomicAdd(&g_cur[dst[e]], 1);
        g_ord[p] = e;
    }
}

// ---------------- K1: first equivariant Linear ----------------
__global__ void k_lin1(const float* __restrict__ nsc, const float* __restrict__ nvec,
                       const float* __restrict__ W1sf, const float* __restrict__ W1ssw,
                       const float* __restrict__ W1vf, const float* __restrict__ W1vs) {
    __shared__ float wsf[1024], wss[1024], wvf[1024], wvs[1024];
    int t = threadIdx.x;
    for (int i = t; i < 1024; i += 256) {
        wsf[i] = W1sf[i];
        wss[i] = W1ssw[i];
        wvf[i] = W1vf[i];
        wvs[i] = W1vs[i];
    }
    __syncthreads();
    int warp = t >> 5, lane = t & 31;
    int n = blockIdx.x * 8 + warp;

    float s_l  = nsc[n * 32 + lane];
    int   b3l  = (n * 32 + lane) * 3;
    float vx_l = nvec[b3l + 0];
    float vy_l = nvec[b3l + 1];
    float vz_l = nvec[b3l + 2];

    float fs = 0.f, ss = 0.f;
    float fvx = 0.f, fvy = 0.f, fvz = 0.f;
    float svx = 0.f, svy = 0.f, svz = 0.f;
#pragma unroll
    for (int u = 0; u < 32; u++) {
        float s  = __shfl_sync(0xffffffffu, s_l, u);
        float vx = __shfl_sync(0xffffffffu, vx_l, u);
        float vy = __shfl_sync(0xffffffffu, vy_l, u);
        float vz = __shfl_sync(0xffffffffu, vz_l, u);
        float a = wsf[u * 32 + lane];
        float b = wss[u * 32 + lane];
        float c = wvf[u * 32 + lane];
        float d = wvs[u * 32 + lane];
        fs += s * a;
        ss += s * b;
        fvx += vx * c; fvy += vy * c; fvz += vz * c;
        svx += vx * d; svy += vy * d; svz += vz * d;
    }
    const float inv = 0.17677669529663687f;  // 1/sqrt(32)
    g_fs[n * 32 + lane] = fs * inv;
    g_ss[n * 32 + lane] = ss * inv;
    int b3 = (n * 32 + lane) * 3;
    g_fv[b3 + 0] = fvx * inv; g_fv[b3 + 1] = fvy * inv; g_fv[b3 + 2] = fvz * inv;
    g_sv[b3 + 0] = svx * inv; g_sv[b3 + 1] = svy * inv; g_sv[b3 + 2] = svz * inv;
}

// ---------------- K2a: radial MLP, 1 edge/thread, f32x2 packed over OUTPUT dim ----
// Every 64-bit register holds two ADJACENT output channels of the same edge,
// so h[] needs only 32 b64 regs (64 fp32 regs) — no spills — while every MAC
// is still an FFMA2.
// smem (all pre-packed b64):
//   wm0P [32][16] : pairs (Wmlp0[k][2a], Wmlp0[k][2a+1])   4 KB
//   wm1P [64][32] : pairs (Wmlp1[k2][2j], Wmlp1[k2][2j+1]) 16 KB
//   wiP  [64][64] : pairs of adjacent cols of [Wi0|Wi1|Wi2|Wi3] 32 KB
__global__ void __launch_bounds__(256) k_mlp(const float* __restrict__ esa,
                                             const float* __restrict__ Wmlp0,
                                             const float* __restrict__ Wmlp1,
                                             const float* __restrict__ Wi0,
                                             const float* __restrict__ Wi1,
                                             const float* __restrict__ Wi2,
                                             const float* __restrict__ Wi3) {
    extern __shared__ ull smp[];
    ull* wm0P = smp;           // 512 ull
    ull* wm1P = smp + 512;     // 2048 ull
    ull* wiP  = smp + 2560;    // 4096 ull
    int t = threadIdx.x;
    for (int i = t; i < 512; i += 256) {
        int a = i >> 4, k = i & 15;
        wm0P[a * 16 + k] = pk2(Wmlp0[k * 64 + 2 * a], Wmlp0[k * 64 + 2 * a + 1]);
    }
    for (int i = t; i < 2048; i += 256) {
        float2 v = ((const float2*)Wmlp1)[i];   // [k2][j2] pairs, contiguous
        wm1P[i] = pk2(v.x, v.y);
    }
    for (int i = t; i < 4096; i += 256) {
        int k = i >> 6, m2 = i & 63;
        int sel = m2 >> 4, off = m2 & 15;
        const float* W = (sel == 0) ? Wi0 : (sel == 1) ? Wi1 : (sel == 2) ? Wi2 : Wi3;
        float2 v = ((const float2*)W)[k * 16 + off];
        wiP[i] = pk2(v.x, v.y);
    }
    __syncthreads();

    int e = blockIdx.x * 256 + t;

    // input, dup-packed (both halves identical)
    ull xd[16];
    {
        const float4* p = (const float4*)(esa + (size_t)e * 16);
#pragma unroll
        for (int q = 0; q < 4; q++) {
            float4 a = p[q];
            xd[q * 4 + 0] = pk2(a.x, a.x);
            xd[q * 4 + 1] = pk2(a.y, a.y);
            xd[q * 4 + 2] = pk2(a.z, a.z);
            xd[q * 4 + 3] = pk2(a.w, a.w);
        }
    }

    const ull E2 = pk2(0.125f, 0.125f);  // 1/sqrt(64)

    ull h[32];   // packed pairs of hidden units
#pragma unroll
    for (int j = 0; j < 32; j++) h[j] = 0ull;

    // fused stage1 + stage2: two hidden units (one pair) at a time
    for (int a = 0; a < 32; a++) {
        ull t0p = 0ull;
        const ulonglong2* wc = (const ulonglong2*)(wm0P + a * 16);
#pragma unroll
        for (int kq = 0; kq < 8; kq++) {
            ulonglong2 w = wc[kq];
            t0p = fma2(xd[kq * 2 + 0], w.x, t0p);
            t0p = fma2(xd[kq * 2 + 1], w.y, t0p);
        }
        float t0a, t0b; upk2(t0p, t0a, t0b);
        t0a = gelu_f(t0a * 0.25f);   // /sqrt(16)
        t0b = gelu_f(t0b * 0.25f);
        ull da = pk2(t0a, t0a);
        ull db = pk2(t0b, t0b);
        const ulonglong2* ra = (const ulonglong2*)(wm1P + (2 * a) * 32);
        const ulonglong2* rb = (const ulonglong2*)(wm1P + (2 * a + 1) * 32);
#pragma unroll
        for (int j2 = 0; j2 < 16; j2++) {
            ulonglong2 wa = ra[j2];
            ulonglong2 wb = rb[j2];
            h[j2 * 2 + 0] = fma2(da, wa.x, h[j2 * 2 + 0]);
            h[j2 * 2 + 1] = fma2(da, wa.y, h[j2 * 2 + 1]);
            h[j2 * 2 + 0] = fma2(db, wb.x, h[j2 * 2 + 0]);
            h[j2 * 2 + 1] = fma2(db, wb.y, h[j2 * 2 + 1]);
        }
    }
#pragma unroll
    for (int j = 0; j < 32; j++) h[j] = gelu2(mul2(h[j], E2));  // /sqrt(64)

    // stage3: 64 packed outputs in chunks of 8 pairs (16 floats)
    float* wout = g_w + (size_t)e * 128;
#pragma unroll 1
    for (int c = 0; c < 8; c++) {
        ull acc[8];
#pragma unroll
        for (int q = 0; q < 8; q++) acc[q] = 0ull;
        const ull* wb = wiP + c * 8;
#pragma unroll
        for (int k2 = 0; k2 < 32; k2++) {
            float ha, hb; upk2(h[k2], ha, hb);
            ull hda = pk2(ha, ha);
            ull hdb = pk2(hb, hb);
            const ulonglong2* wka = (const ulonglong2*)(wb + (2 * k2) * 64);
            const ulonglong2* wkb = (const ulonglong2*)(wb + (2 * k2 + 1) * 64);
            ulonglong2 a0 = wka[0], a1 = wka[1], a2 = wka[2], a3 = wka[3];
            acc[0] = fma2(hda, a0.x, acc[0]);
            acc[1] = fma2(hda, a0.y, acc[1]);
            acc[2] = fma2(hda, a1.x, acc[2]);
            acc[3] = fma2(hda, a1.y, acc[3]);
            acc[4] = fma2(hda, a2.x, acc[4]);
            acc[5] = fma2(hda, a2.y, acc[5]);
            acc[6] = fma2(hda, a3.x, acc[6]);
            acc[7] = fma2(hda, a3.y, acc[7]);
            ulonglong2 b0 = wkb[0], b1 = wkb[1], b2 = wkb[2], b3 = wkb[3];
            acc[0] = fma2(hdb, b0.x, acc[0]);
            acc[1] = fma2(hdb, b0.y, acc[1]);
            acc[2] = fma2(hdb, b1.x, acc[2]);
            acc[3] = fma2(hdb, b1.y, acc[3]);
            acc[4] = fma2(hdb, b2.x, acc[4]);
            acc[5] = fma2(hdb, b2.y, acc[5]);
            acc[6] = fma2(hdb, b3.x, acc[6]);
            acc[7] = fma2(hdb, b3.y, acc[7]);
        }
        ull* po = (ull*)(wout + c * 16);  // 16 floats = 8 packed pairs
#pragma unroll
        for (int q = 0; q < 8; q++) po[q] = mul2(acc[q], E2);  // /sqrt(64)
    }
}

// ---------------- K2b: gather + tensor product + segment reduce ----------------
__global__ void k_gather(const float* __restrict__ eas, const float* __restrict__ eav,
                         const int* __restrict__ src) {
    int t = threadIdx.x;
    int n = (blockIdx.x * blockDim.x + t) >> 5;
    int lane = t & 31;
    int beg = g_row[n], end = g_row[n + 1];

    float a0 = 0.f, a3 = 0.f;
    float a1x = 0.f, a1y = 0.f, a1z = 0.f;
    float a2x = 0.f, a2y = 0.f, a2z = 0.f;

    for (int base = beg; base < end; base += 32) {
        int cnt = min(32, end - base);
        int idx = 0, s = 0;
        float vx = 0.f, vy = 0.f, vz = 0.f, ea = 0.f;
        if (lane < cnt) {
            idx = g_ord[base + lane];
            s = src[idx];
            vx = eav[idx * 3 + 0];
            vy = eav[idx * 3 + 1];
            vz = eav[idx * 3 + 2];
            ea = eas[idx];
        }
        for (int i = 0; i < cnt; i++) {
            int ide = __shfl_sync(0xffffffffu, idx, i);
            int se  = __shfl_sync(0xffffffffu, s, i);
            float evx = __shfl_sync(0xffffffffu, vx, i);
            float evy = __shfl_sync(0xffffffffu, vy, i);
            float evz = __shfl_sync(0xffffffffu, vz, i);
            float eae = __shfl_sync(0xffffffffu, ea, i);

            const float* wp = g_w + (size_t)ide * 128;
            float w0 = wp[lane];
            float w1 = wp[32 + lane];
            float w2 = wp[64 + lane];
            float w3 = wp[96 + lane];
            float es = g_fs[se * 32 + lane];
            int b3 = (se * 32 + lane) * 3;
            float fx = g_fv[b3 + 0];
            float fy = g_fv[b3 + 1];
            float fz = g_fv[b3 + 2];

            float dot = fx * evx + fy * evy + fz * evz;
            a0 += w0 * es * eae;
            a3 += w3 * dot;
            float w1es = w1 * es;
            a1x += w1es * evx; a1y += w1es * evy; a1z += w1es * evz;
            float w2ea = w2 * eae;
            a2x += w2ea * fx; a2y += w2ea * fy; a2z += w2ea * fz;
        }
    }

    const float inv_nb = 0.17677669529663687f;  // 1/sqrt(32)
    const float inv_s3 = 0.5773502691896258f;   // 1/sqrt(3)
    g_ns[n * 64 + lane]      = a0 * inv_nb;
    g_ns[n * 64 + 32 + lane] = a3 * inv_s3 * inv_nb;
    int ba = n * 192 + lane * 3;
    g_nv[ba + 0] = a1x * inv_nb; g_nv[ba + 1] = a1y * inv_nb; g_nv[ba + 2] = a1z * inv_nb;
    int bb = n * 192 + (32 + lane) * 3;
    g_nv[bb + 0] = a2x * inv_nb; g_nv[bb + 1] = a2y * inv_nb; g_nv[bb + 2] = a2z * inv_nb;
}

// ---------------- K3: second Linear + self-connection mix ----------------
__global__ void k_lin2(const float* __restrict__ W2s, const float* __restrict__ W2v,
                       float* __restrict__ out) {
    __shared__ float w2s[2048], w2v[2048];
    int t = threadIdx.x;
    for (int i = t; i < 2048; i += 256) {
        w2s[i] = W2s[i];
        w2v[i] = W2v[i];
    }
    __syncthreads();
    int warp = t >> 5, lane = t & 31;
    int n = blockIdx.x * 8 + warp;

    float nsa = g_ns[n * 64 + lane];
    float nsb = g_ns[n * 64 + 32 + lane];
    int ba = n * 192 + lane * 3;
    int bb = n * 192 + (32 + lane) * 3;
    float vax = g_nv[ba + 0], vay = g_nv[ba + 1], vaz = g_nv[ba + 2];
    float vbx = g_nv[bb + 0], vby = g_nv[bb + 1], vbz = g_nv[bb + 2];

    float cs = 0.f, cvx = 0.f, cvy = 0.f, cvz = 0.f;
#pragma unroll
    for (int j = 0; j < 32; j++) {
        float sj = __shfl_sync(0xffffffffu, nsa, j);
        float xj = __shfl_sync(0xffffffffu, vax, j);
        float yj = __shfl_sync(0xffffffffu, vay, j);
        float zj = __shfl_sync(0xffffffffu, vaz, j);
        float ws = w2s[j * 32 + lane];
        float wv = w2v[j * 32 + lane];
        cs += sj * ws;
        cvx += xj * wv; cvy += yj * wv; cvz += zj * wv;
    }
#pragma unroll
    for (int j = 0; j < 32; j++) {
        float sj = __shfl_sync(0xffffffffu, nsb, j);
        float xj = __shfl_sync(0xffffffffu, vbx, j);
        float yj = __shfl_sync(0xffffffffu, vby, j);
        float zj = __shfl_sync(0xffffffffu, vbz, j);
        float ws = w2s[(32 + j) * 32 + lane];
        float wv = w2v[(32 + j) * 32 + lane];
        cs += sj * ws;
        cvx += xj * wv; cvy += yj * wv; cvz += zj * wv;
    }
    const float inv_mid = 0.125f;                 // 1/sqrt(64)
    const float cc = 0.9238795325112867f;         // cos(pi/8)
    const float sc = 0.3826834323650898f;         // sin(pi/8)
    float ssv = g_ss[n * 32 + lane];
    out[n * 32 + lane] = cc * ssv + sc * cs * inv_mid;

    int b3 = (n * 32 + lane) * 3;
    float* ov = out + NN * 32;
    ov[b3 + 0] = cc * g_sv[b3 + 0] + sc * cvx * inv_mid;
    ov[b3 + 1] = cc * g_sv[b3 + 1] + sc * cvy * inv_mid;
    ov[b3 + 2] = cc * g_sv[b3 + 2] + sc * cvz * inv_mid;
}

// ---------------- launch ----------------
extern "C" void kernel_launch(void* const* d_in, const int* in_sizes, int n_in,
                              void* d_out, int out_size) {
    const float* node_scalars = (const float*)d_in[0];
    const float* node_vectors = (const float*)d_in[1];
    const float* edge_attr_s  = (const float*)d_in[2];
    const float* edge_attr_v  = (const float*)d_in[3];
    const float* edge_scalar  = (const float*)d_in[4];
    const int*   edge_src     = (const int*)d_in[5];
    const int*   edge_dst     = (const int*)d_in[6];
    const float* W1s_feat     = (const float*)d_in[7];
    const float* W1s_self     = (const float*)d_in[8];
    const float* W1v_feat     = (const float*)d_in[9];
    const float* W1v_self     = (const float*)d_in[10];
    const float* Wmlp0        = (const float*)d_in[11];
    const float* Wmlp1        = (const float*)d_in[12];
    const float* Wi0          = (const float*)d_in[13];
    const float* Wi1          = (const float*)d_in[14];
    const float* Wi2          = (const float*)d_in[15];
    const float* Wi3          = (const float*)d_in[16];
    const float* W2s          = (const float*)d_in[17];
    const float* W2v          = (const float*)d_in[18];
    float* out = (float*)d_out;

    static bool attr_set = false;
    if (!attr_set) {
        cudaFuncSetAttribute(k_mlp, cudaFuncAttributeMaxDynamicSharedMemorySize, 6656 * 8);
        attr_set = true;
    }

    // sort edges by destination
    k_zero<<<(NN + 255) / 256, 256>>>();
    k_hist<<<EE / 256, 256>>>(edge_dst);
    k_scan<<<1, 1024>>>();
    k_place<<<EE / 256, 256>>>(edge_dst);

    // node linear 1
    k_lin1<<<NN / 8, 256>>>(node_scalars, node_vectors, W1s_feat, W1s_self, W1v_feat, W1v_self);

    // per-edge radial MLP (f32x2 packed over output channels)
    k_mlp<<<EE / 256, 256, 6656 * 8>>>(edge_scalar, Wmlp0, Wmlp1, Wi0, Wi1, Wi2, Wi3);

    // gather + tensor product + segment sum
    k_gather<<<(NN * 32) / 256, 256>>>(edge_attr_s, edge_attr_v, edge_src);

    // node linear 2 + mix
    k_lin2<<<NN / 8, 256>>>(W2s, W2v, out);
}

// round 4
// speedup vs baseline: 1.6388x; 1.6388x over previous
#include <cuda_runtime.h>
#include <math.h>

#define NN 20000
#define EE 640000

// ---------------- scratch (device globals; no allocation) ----------------
__device__ float g_fs[NN * 32];
__device__ float g_ss[NN * 32];
__device__ float g_fv[NN * 96];
__device__ float g_sv[NN * 96];
__device__ float g_w[(size_t)EE * 128];  // per-edge MLP weights [E][4*32]
__device__ float g_ns[NN * 64];
__device__ float g_nv[NN * 192];
__device__ int   g_cnt[NN];
__device__ int   g_row[NN + 1];
__device__ int   g_cur[NN];
__device__ int   g_ord[EE];

// ---------------- helpers ----------------
__device__ __forceinline__ float tanh_ap(float x) {
    float r; asm("tanh.approx.f32 %0,%1;" : "=f"(r) : "f"(x)); return r;
}
__device__ __forceinline__ float gelu_f(float v) {
    float u = 0.7978845608028654f * (v + 0.044715f * v * v * v);
    return 0.5f * v * (1.0f + tanh_ap(u));
}
__device__ __forceinline__ unsigned cvt_tf32(float x) {
    unsigned r; asm("cvt.rna.tf32.f32 %0,%1;" : "=r"(r) : "f"(x)); return r;
}
__device__ __forceinline__ void mma_tf32(float& c0, float& c1, float& c2, float& c3,
                                         unsigned a0, unsigned a1, unsigned a2, unsigned a3,
                                         unsigned b0, unsigned b1) {
    asm volatile("mma.sync.aligned.m16n8k8.row.col.f32.tf32.tf32.f32 "
                 "{%0,%1,%2,%3},{%4,%5,%6,%7},{%8,%9},{%0,%1,%2,%3};"
                 : "+f"(c0), "+f"(c1), "+f"(c2), "+f"(c3)
                 : "r"(a0), "r"(a1), "r"(a2), "r"(a3), "r"(b0), "r"(b1));
}
// C-fragment (m16n8) of one 8-col tile -> A-fragment (m16k8) of next GEMM.
// c0:(g,2t) c1:(g,2t+1) c2:(g+8,2t) c3:(g+8,2t+1) -> a0:(g,t) a1:(g+8,t) a2:(g,t+4) a3:(g+8,t+4)
__device__ __forceinline__ void refrag(float f0, float f1, float f2, float f3,
                                       int lane, int tig,
                                       unsigned& a0, unsigned& a1, unsigned& a2, unsigned& a3) {
    unsigned s0 = cvt_tf32(f0), s1 = cvt_tf32(f1), s2 = cvt_tf32(f2), s3 = cvt_tf32(f3);
    const unsigned m = 0xffffffffu;
    int base = lane & ~3;
    int src0 = base | (tig >> 1);
    int src1 = base | ((tig >> 1) + 2);
    unsigned e0a = __shfl_sync(m, s0, src0), e1a = __shfl_sync(m, s1, src0);
    unsigned e0b = __shfl_sync(m, s0, src1), e1b = __shfl_sync(m, s1, src1);
    unsigned o0a = __shfl_sync(m, s2, src0), o1a = __shfl_sync(m, s3, src0);
    unsigned o0b = __shfl_sync(m, s2, src1), o1b = __shfl_sync(m, s3, src1);
    bool odd = (tig & 1);
    a0 = odd ? e1a : e0a;
    a2 = odd ? e1b : e0b;
    a1 = odd ? o1a : o0a;
    a3 = odd ? o1b : o0b;
}

// ---------------- sort-by-dst machinery ----------------
__global__ void k_zero() {
    int i = blockIdx.x * blockDim.x + threadIdx.x;
    if (i < NN) g_cnt[i] = 0;
}
__global__ void k_hist(const int* __restrict__ dst) {
    int e = blockIdx.x * blockDim.x + threadIdx.x;
    if (e < EE) atomicAdd(&g_cnt[dst[e]], 1);
}
__global__ void k_scan() {
    __shared__ int part[1024];
    int t = threadIdx.x;
    const int CH = (NN + 1023) / 1024;
    int base = t * CH;
    int s = 0;
    for (int i = 0; i < CH; i++) {
        int idx = base + i;
        if (idx < NN) s += g_cnt[idx];
    }
    part[t] = s;
    __syncthreads();
    for (int off = 1; off < 1024; off <<= 1) {
        int v = 0;
        if (t >= off) v = part[t - off];
        __syncthreads();
        part[t] += v;
        __syncthreads();
    }
    int run = (t == 0) ? 0 : part[t - 1];
    for (int i = 0; i < CH; i++) {
        int idx = base + i;
        if (idx < NN) {
            g_row[idx] = run;
            g_cur[idx] = run;
            run += g_cnt[idx];
        }
    }
    if (t == 1023) g_row[NN] = part[1023];
}
__global__ void k_place(const int* __restrict__ dst) {
    int e = blockIdx.x * blockDim.x + threadIdx.x;
    if (e < EE) {
        int p = atomicAdd(&g_cur[dst[e]], 1);
        g_ord[p] = e;
    }
}

// ---------------- K1: first equivariant Linear ----------------
__global__ void k_lin1(const float* __restrict__ nsc, const float* __restrict__ nvec,
                       const float* __restrict__ W1sf, const float* __restrict__ W1ssw,
                       const float* __restrict__ W1vf, const float* __restrict__ W1vs) {
    __shared__ float wsf[1024], wss[1024], wvf[1024], wvs[1024];
    int t = threadIdx.x;
    for (int i = t; i < 1024; i += 256) {
        wsf[i] = W1sf[i];
        wss[i] = W1ssw[i];
        wvf[i] = W1vf[i];
        wvs[i] = W1vs[i];
    }
    __syncthreads();
    int warp = t >> 5, lane = t & 31;
    int n = blockIdx.x * 8 + warp;

    float s_l  = nsc[n * 32 + lane];
    int   b3l  = (n * 32 + lane) * 3;
    float vx_l = nvec[b3l + 0];
    float vy_l = nvec[b3l + 1];
    float vz_l = nvec[b3l + 2];

    float fs = 0.f, ss = 0.f;
    float fvx = 0.f, fvy = 0.f, fvz = 0.f;
    float svx = 0.f, svy = 0.f, svz = 0.f;
#pragma unroll
    for (int u = 0; u < 32; u++) {
        float s  = __shfl_sync(0xffffffffu, s_l, u);
        float vx = __shfl_sync(0xffffffffu, vx_l, u);
        float vy = __shfl_sync(0xffffffffu, vy_l, u);
        float vz = __shfl_sync(0xffffffffu, vz_l, u);
        float a = wsf[u * 32 + lane];
        float b = wss[u * 32 + lane];
        float c = wvf[u * 32 + lane];
        float d = wvs[u * 32 + lane];
        fs += s * a;
        ss += s * b;
        fvx += vx * c; fvy += vy * c; fvz += vz * c;
        svx += vx * d; svy += vy * d; svz += vz * d;
    }
    const float inv = 0.17677669529663687f;  // 1/sqrt(32)
    g_fs[n * 32 + lane] = fs * inv;
    g_ss[n * 32 + lane] = ss * inv;
    int b3 = (n * 32 + lane) * 3;
    g_fv[b3 + 0] = fvx * inv; g_fv[b3 + 1] = fvy * inv; g_fv[b3 + 2] = fvz * inv;
    g_sv[b3 + 0] = svx * inv; g_sv[b3 + 1] = svy * inv; g_sv[b3 + 2] = svz * inv;
}

// ---------------- K2a: radial MLP via tf32 tensor cores ----------------
// Block = 128 edges; warp owns a 16-edge row slice. Three chained GEMMs,
// activations stay in registers; C->A refragmentation via quad shuffles.
// smem strides padded (17/68/132) for conflict-free B-fragment loads.
__global__ void __launch_bounds__(256) k_mlp(const float* __restrict__ esa,
                                             const float* __restrict__ Wmlp0,
                                             const float* __restrict__ Wmlp1,
                                             const float* __restrict__ Wi0,
                                             const float* __restrict__ Wi1,
                                             const float* __restrict__ Wi2,
                                             const float* __restrict__ Wi3) {
    extern __shared__ unsigned sm[];
    unsigned* Xs  = sm;                     // [128][17]
    unsigned* W0s = sm + 128 * 17;          // [16][68]
    unsigned* W1s = W0s + 16 * 68;          // [64][68]
    unsigned* WIs = W1s + 64 * 68;          // [64][132]
    int t = threadIdx.x;

    for (int i = t; i < 16 * 64; i += 256) {
        int k = i >> 6, n = i & 63;
        W0s[k * 68 + n] = cvt_tf32(Wmlp0[i]);
    }
    for (int i = t; i < 64 * 64; i += 256) {
        int k = i >> 6, n = i & 63;
        W1s[k * 68 + n] = cvt_tf32(Wmlp1[i]);
    }
    for (int i = t; i < 64 * 128; i += 256) {
        int k = i >> 7, n = i & 127;
        int sel = n >> 5, u = n & 31;
        const float* W = (sel == 0) ? Wi0 : (sel == 1) ? Wi1 : (sel == 2) ? Wi2 : Wi3;
        WIs[k * 132 + n] = cvt_tf32(W[k * 32 + u]);
    }
    int e0 = blockIdx.x * 128;
    for (int i = t; i < 2048; i += 256) {
        int m = i >> 4, k = i & 15;
        Xs[m * 17 + k] = cvt_tf32(esa[(size_t)(e0 + m) * 16 + k]);
    }
    __syncthreads();

    int warp = t >> 5, lane = t & 31;
    int g = lane >> 2, tig = lane & 3;
    int m0 = warp * 16;

    // ---- GEMM1: [16,16] x [16,64] ----
    unsigned a1f[2][4];
#pragma unroll
    for (int ks = 0; ks < 2; ks++) {
        a1f[ks][0] = Xs[(m0 + g) * 17 + ks * 8 + tig];
        a1f[ks][1] = Xs[(m0 + g + 8) * 17 + ks * 8 + tig];
        a1f[ks][2] = Xs[(m0 + g) * 17 + ks * 8 + tig + 4];
        a1f[ks][3] = Xs[(m0 + g + 8) * 17 + ks * 8 + tig + 4];
    }
    unsigned A2[8][4];
#pragma unroll
    for (int n = 0; n < 8; n++) {
        float c0 = 0.f, c1 = 0.f, c2 = 0.f, c3 = 0.f;
#pragma unroll
        for (int ks = 0; ks < 2; ks++) {
            unsigned b0 = W0s[(ks * 8 + tig) * 68 + n * 8 + g];
            unsigned b1 = W0s[(ks * 8 + tig + 4) * 68 + n * 8 + g];
            mma_tf32(c0, c1, c2, c3, a1f[ks][0], a1f[ks][1], a1f[ks][2], a1f[ks][3], b0, b1);
        }
        // gelu(x/sqrt(16)) then refragment into A for GEMM2 (k-step = n)
        refrag(gelu_f(c0 * 0.25f), gelu_f(c1 * 0.25f), gelu_f(c2 * 0.25f), gelu_f(c3 * 0.25f),
               lane, tig, A2[n][0], A2[n][1], A2[n][2], A2[n][3]);
    }

    // ---- GEMM2: [16,64] x [64,64] ----
    unsigned A3[8][4];
#pragma unroll
    for (int n = 0; n < 8; n++) {
        float c0 = 0.f, c1 = 0.f, c2 = 0.f, c3 = 0.f;
#pragma unroll
        for (int ks = 0; ks < 8; ks++) {
            unsigned b0 = W1s[(ks * 8 + tig) * 68 + n * 8 + g];
            unsigned b1 = W1s[(ks * 8 + tig + 4) * 68 + n * 8 + g];
            mma_tf32(c0, c1, c2, c3, A2[ks][0], A2[ks][1], A2[ks][2], A2[ks][3], b0, b1);
        }
        refrag(gelu_f(c0 * 0.125f), gelu_f(c1 * 0.125f), gelu_f(c2 * 0.125f), gelu_f(c3 * 0.125f),
               lane, tig, A3[n][0], A3[n][1], A3[n][2], A3[n][3]);
    }

    // ---- GEMM3: [16,64] x [64,128] -> g_w ----
    int row0 = e0 + m0 + g;
    int row1 = row0 + 8;
#pragma unroll
    for (int n = 0; n < 16; n++) {
        float c0 = 0.f, c1 = 0.f, c2 = 0.f, c3 = 0.f;
#pragma unroll
        for (int ks = 0; ks < 8; ks++) {
            unsigned b0 = WIs[(ks * 8 + tig) * 132 + n * 8 + g];
            unsigned b1 = WIs[(ks * 8 + tig + 4) * 132 + n * 8 + g];
            mma_tf32(c0, c1, c2, c3, A3[ks][0], A3[ks][1], A3[ks][2], A3[ks][3], b0, b1);
        }
        const float s8 = 0.125f;  // /sqrt(64)
        int col = n * 8 + 2 * tig;
        *(float2*)(g_w + (size_t)row0 * 128 + col) = make_float2(c0 * s8, c1 * s8);
        *(float2*)(g_w + (size_t)row1 * 128 + col) = make_float2(c2 * s8, c3 * s8);
    }
}

// ---------------- K2b: gather + tensor product + segment reduce ----------------
__global__ void k_gather(const float* __restrict__ eas, const float* __restrict__ eav,
                         const int* __restrict__ src) {
    int t = threadIdx.x;
    int n = (blockIdx.x * blockDim.x + t) >> 5;
    int lane = t & 31;
    int beg = g_row[n], end = g_row[n + 1];

    float a0 = 0.f, a3 = 0.f;
    float a1x = 0.f, a1y = 0.f, a1z = 0.f;
    float a2x = 0.f, a2y = 0.f, a2z = 0.f;

    for (int base = beg; base < end; base += 32) {
        int cnt = min(32, end - base);
        int idx = 0, s = 0;
        float vx = 0.f, vy = 0.f, vz = 0.f, ea = 0.f;
        if (lane < cnt) {
            idx = g_ord[base + lane];
            s = src[idx];
            vx = eav[idx * 3 + 0];
            vy = eav[idx * 3 + 1];
            vz = eav[idx * 3 + 2];
            ea = eas[idx];
        }
        for (int i = 0; i < cnt; i++) {
            int ide = __shfl_sync(0xffffffffu, idx, i);
            int se  = __shfl_sync(0xffffffffu, s, i);
            float evx = __shfl_sync(0xffffffffu, vx, i);
            float evy = __shfl_sync(0xffffffffu, vy, i);
            float evz = __shfl_sync(0xffffffffu, vz, i);
            float eae = __shfl_sync(0xffffffffu, ea, i);

            const float* wp = g_w + (size_t)ide * 128;
            float w0 = wp[lane];
            float w1 = wp[32 + lane];
            float w2 = wp[64 + lane];
            float w3 = wp[96 + lane];
            float es = g_fs[se * 32 + lane];
            int b3 = (se * 32 + lane) * 3;
            float fx = g_fv[b3 + 0];
            float fy = g_fv[b3 + 1];
            float fz = g_fv[b3 + 2];

            float dot = fx * evx + fy * evy + fz * evz;
            a0 += w0 * es * eae;
            a3 += w3 * dot;
            float w1es = w1 * es;
            a1x += w1es * evx; a1y += w1es * evy; a1z += w1es * evz;
            float w2ea = w2 * eae;
            a2x += w2ea * fx; a2y += w2ea * fy; a2z += w2ea * fz;
        }
    }

    const float inv_nb = 0.17677669529663687f;  // 1/sqrt(32)
    const float inv_s3 = 0.5773502691896258f;   // 1/sqrt(3)
    g_ns[n * 64 + lane]      = a0 * inv_nb;
    g_ns[n * 64 + 32 + lane] = a3 * inv_s3 * inv_nb;
    int ba = n * 192 + lane * 3;
    g_nv[ba + 0] = a1x * inv_nb; g_nv[ba + 1] = a1y * inv_nb; g_nv[ba + 2] = a1z * inv_nb;
    int bb = n * 192 + (32 + lane) * 3;
    g_nv[bb + 0] = a2x * inv_nb; g_nv[bb + 1] = a2y * inv_nb; g_nv[bb + 2] = a2z * inv_nb;
}

// ---------------- K3: second Linear + self-connection mix ----------------
__global__ void k_lin2(const float* __restrict__ W2s, const float* __restrict__ W2v,
                       float* __restrict__ out) {
    __shared__ float w2s[2048], w2v[2048];
    int t = threadIdx.x;
    for (int i = t; i < 2048; i += 256) {
        w2s[i] = W2s[i];
        w2v[i] = W2v[i];
    }
    __syncthreads();
    int warp = t >> 5, lane = t & 31;
    int n = blockIdx.x * 8 + warp;

    float nsa = g_ns[n * 64 + lane];
    float nsb = g_ns[n * 64 + 32 + lane];
    int ba = n * 192 + lane * 3;
    int bb = n * 192 + (32 + lane) * 3;
    float vax = g_nv[ba + 0], vay = g_nv[ba + 1], vaz = g_nv[ba + 2];
    float vbx = g_nv[bb + 0], vby = g_nv[bb + 1], vbz = g_nv[bb + 2];

    float cs = 0.f, cvx = 0.f, cvy = 0.f, cvz = 0.f;
#pragma unroll
    for (int j = 0; j < 32; j++) {
        float sj = __shfl_sync(0xffffffffu, nsa, j);
        float xj = __shfl_sync(0xffffffffu, vax, j);
        float yj = __shfl_sync(0xffffffffu, vay, j);
        float zj = __shfl_sync(0xffffffffu, vaz, j);
        float ws = w2s[j * 32 + lane];
        float wv = w2v[j * 32 + lane];
        cs += sj * ws;
        cvx += xj * wv; cvy += yj * wv; cvz += zj * wv;
    }
#pragma unroll
    for (int j = 0; j < 32; j++) {
        float sj = __shfl_sync(0xffffffffu, nsb, j);
        float xj = __shfl_sync(0xffffffffu, vbx, j);
        float yj = __shfl_sync(0xffffffffu, vby, j);
        float zj = __shfl_sync(0xffffffffu, vbz, j);
        float ws = w2s[(32 + j) * 32 + lane];
        float wv = w2v[(32 + j) * 32 + lane];
        cs += sj * ws;
        cvx += xj * wv; cvy += yj * wv; cvz += zj * wv;
    }
    const float inv_mid = 0.125f;                 // 1/sqrt(64)
    const float cc = 0.9238795325112867f;         // cos(pi/8)
    const float sc = 0.3826834323650898f;         // sin(pi/8)
    float ssv = g_ss[n * 32 + lane];
    out[n * 32 + lane] = cc * ssv + sc * cs * inv_mid;

    int b3 = (n * 32 + lane) * 3;
    float* ov = out + NN * 32;
    ov[b3 + 0] = cc * g_sv[b3 + 0] + sc * cvx * inv_mid;
    ov[b3 + 1] = cc * g_sv[b3 + 1] + sc * cvy * inv_mid;
    ov[b3 + 2] = cc * g_sv[b3 + 2] + sc * cvz * inv_mid;
}

// ---------------- launch ----------------
extern "C" void kernel_launch(void* const* d_in, const int* in_sizes, int n_in,
                              void* d_out, int out_size) {
    const float* node_scalars = (const float*)d_in[0];
    const float* node_vectors = (const float*)d_in[1];
    const float* edge_attr_s  = (const float*)d_in[2];
    const float* edge_attr_v  = (const float*)d_in[3];
    const float* edge_scalar  = (const float*)d_in[4];
    const int*   edge_src     = (const int*)d_in[5];
    const int*   edge_dst     = (const int*)d_in[6];
    const float* W1s_feat     = (const float*)d_in[7];
    const float* W1s_self     = (const float*)d_in[8];
    const float* W1v_feat     = (const float*)d_in[9];
    const float* W1v_self     = (const float*)d_in[10];
    const float* Wmlp0        = (const float*)d_in[11];
    const float* Wmlp1        = (const float*)d_in[12];
    const float* Wi0          = (const float*)d_in[13];
    const float* Wi1          = (const float*)d_in[14];
    const float* Wi2          = (const float*)d_in[15];
    const float* Wi3          = (const float*)d_in[16];
    const float* W2s          = (const float*)d_in[17];
    const float* W2v          = (const float*)d_in[18];
    float* out = (float*)d_out;

    const int MLP_SMEM = (128 * 17 + 16 * 68 + 64 * 68 + 64 * 132) * 4;  // 64256 B

    static bool attr_set = false;
    if (!attr_set) {
        cudaFuncSetAttribute(k_mlp, cudaFuncAttributeMaxDynamicSharedMemorySize, MLP_SMEM);
        attr_set = true;
    }

    // sort edges by destination
    k_zero<<<(NN + 255) / 256, 256>>>();
    k_hist<<<EE / 256, 256>>>(edge_dst);
    k_scan<<<1, 1024>>>();
    k_place<<<EE / 256, 256>>>(edge_dst);

    // node linear 1
    k_lin1<<<NN / 8, 256>>>(node_scalars, node_vectors, W1s_feat, W1s_self, W1v_feat, W1v_self);

    // per-edge radial MLP on tf32 tensor cores (128 edges / block)
    k_mlp<<<EE / 128, 256, MLP_SMEM>>>(edge_scalar, Wmlp0, Wmlp1, Wi0, Wi1, Wi2, Wi3);

    // gather + tensor product + segment sum
    k_gather<<<(NN * 32) / 256, 256>>>(edge_attr_s, edge_attr_v, edge_src);

    // node linear 2 + mix
    k_lin2<<<NN / 8, 256>>>(W2s, W2v, out);
}